// round 1
// baseline (speedup 1.0000x reference)
#include <cuda_runtime.h>

#define NN 4096
#define DD 256
#define WORDS 128   // 4096 bits / 32

// ---------------- scratch (static device memory; no allocation) -------------
__device__ unsigned g_bits[NN * WORDS];   // 2 MB adjacency bitmask
__device__ int      g_is64;
__device__ float    g_q[NN * DD];
__device__ float    g_k[NN * DD];
__device__ float    g_v[NN * DD];
__device__ float    g_vagg[NN * DD];
__device__ float    g_t0[NN * DD];
__device__ float    g_t1[NN * DD];
__device__ float    g_mu[DD];
__device__ float    g_rstd[DD];

// ---------------- graph construction ----------------------------------------
__global__ void k_zero() {
    int i = blockIdx.x * blockDim.x + threadIdx.x;
    if (i < NN * WORDS) g_bits[i] = 0u;
    if (i == 0) g_is64 = 1;
}

// Decide whether edge_index is int64 or int32: if interpreted as int64 the
// first 1024 values must all be in [0, NN). With int32 data the hi halves are
// random node ids (nonzero w.p. 4095/4096 each) so the flag clears.
__global__ void k_detect(const int* __restrict__ e32) {
    int i = blockIdx.x * blockDim.x + threadIdx.x;   // 1024 threads
    int lo = e32[2 * i];
    int hi = e32[2 * i + 1];
    if (hi != 0 || lo < 0 || lo >= NN) atomicAnd(&g_is64, 0);
}

__global__ void k_build(const void* __restrict__ eptr, int E) {
    int i = blockIdx.x * blockDim.x + threadIdx.x;
    if (i >= E) return;
    int r, c;
    if (g_is64) {
        const long long* e = (const long long*)eptr;
        r = (int)e[i];
        c = (int)e[E + i];
    } else {
        const int* e = (const int*)eptr;
        r = e[i];
        c = e[E + i];
    }
    atomicOr(&g_bits[r * WORDS + (c >> 5)], 1u << (c & 31));
}

// ---------------- fp32 tiled GEMM: C[4096,256] = A[4096,256] @ B[256,256] ----
// BM=BN=64, BK=16, 256 threads, 4x4 per thread.
__device__ __forceinline__ void gemm_tile(const float* __restrict__ A,
                                          const float* __restrict__ B,
                                          const float* __restrict__ bias,
                                          float* __restrict__ C,
                                          const float* __restrict__ X,
                                          float eps) {
    __shared__ float As[16][64];
    __shared__ float Bs[16][64];

    int tid = threadIdx.x;
    int tx = tid & 15;        // 0..15 -> col quad
    int ty = tid >> 4;        // 0..15 -> row quad
    int rowBase = blockIdx.y * 64;
    int colBase = blockIdx.x * 64;

    int ar = tid >> 2;            // 0..63
    int ac = (tid & 3) * 4;       // 0,4,8,12
    int br = tid >> 4;            // 0..15
    int bc = (tid & 15) * 4;      // 0..60

    const float* Ag = A + (rowBase + ar) * DD + ac;
    const float* Bg = B + br * DD + colBase + bc;

    float acc[4][4];
#pragma unroll
    for (int i = 0; i < 4; i++)
#pragma unroll
        for (int j = 0; j < 4; j++) acc[i][j] = 0.f;

    for (int kk = 0; kk < DD; kk += 16) {
        float4 a = *(const float4*)(Ag + kk);
        float4 b = *(const float4*)(Bg + kk * DD);
        As[ac + 0][ar] = a.x;
        As[ac + 1][ar] = a.y;
        As[ac + 2][ar] = a.z;
        As[ac + 3][ar] = a.w;
        *(float4*)&Bs[br][bc] = b;
        __syncthreads();
#pragma unroll
        for (int kq = 0; kq < 16; ++kq) {
            float4 av = *(const float4*)&As[kq][ty * 4];
            float4 bv = *(const float4*)&Bs[kq][tx * 4];
            acc[0][0] += av.x * bv.x; acc[0][1] += av.x * bv.y;
            acc[0][2] += av.x * bv.z; acc[0][3] += av.x * bv.w;
            acc[1][0] += av.y * bv.x; acc[1][1] += av.y * bv.y;
            acc[1][2] += av.y * bv.z; acc[1][3] += av.y * bv.w;
            acc[2][0] += av.z * bv.x; acc[2][1] += av.z * bv.y;
            acc[2][2] += av.z * bv.z; acc[2][3] += av.z * bv.w;
            acc[3][0] += av.w * bv.x; acc[3][1] += av.w * bv.y;
            acc[3][2] += av.w * bv.z; acc[3][3] += av.w * bv.w;
        }
        __syncthreads();
    }

    int col0 = colBase + tx * 4;
    float4 bi = *(const float4*)&bias[col0];
#pragma unroll
    for (int i = 0; i < 4; i++) {
        int row = rowBase + ty * 4 + i;
        float4 o;
        o.x = acc[i][0] + bi.x;
        o.y = acc[i][1] + bi.y;
        o.z = acc[i][2] + bi.z;
        o.w = acc[i][3] + bi.w;
        if (X) {
            const float4 xv = *(const float4*)&X[row * DD + col0];
            o.x += eps * xv.x; o.y += eps * xv.y;
            o.z += eps * xv.z; o.w += eps * xv.w;
        }
        *(float4*)&C[row * DD + col0] = o;
    }
}

__global__ void k_gemm_qkv(const float* __restrict__ x,
                           const float* __restrict__ wq, const float* __restrict__ bq,
                           const float* __restrict__ wk, const float* __restrict__ bk,
                           const float* __restrict__ wv, const float* __restrict__ bv) {
    const float* B;
    const float* bi;
    float* C;
    if (blockIdx.z == 0)      { B = wq; bi = bq; C = g_q; }
    else if (blockIdx.z == 1) { B = wk; bi = bk; C = g_k; }
    else                      { B = wv; bi = bv; C = g_v; }
    gemm_tile(x, B, bi, C, nullptr, 0.f);
}

__global__ void k_gemm_wo(const float* __restrict__ wo, const float* __restrict__ bo,
                          const float* __restrict__ x, const float* __restrict__ epsP) {
    gemm_tile(g_vagg, wo, bo, g_t0, x, epsP[0]);
}

__global__ void k_gemm_w1(const float* __restrict__ w1, const float* __restrict__ b1) {
    gemm_tile(g_t0, w1, b1, g_t1, nullptr, 0.f);
}

__global__ void k_gemm_w2(const float* __restrict__ w2, const float* __restrict__ b2) {
    gemm_tile(g_t1, w2, b2, g_t0, nullptr, 0.f);
}

// ---------------- sparse masked attention (one warp per node,head) ----------
__global__ void k_attn() {
    int gw   = (blockIdx.x * blockDim.x + threadIdx.x) >> 5;
    int lane = threadIdx.x & 31;
    if (gw >= NN * 2) return;
    int node = gw >> 1;
    int head = gw & 1;

    const float scale = 0.08838834764831845f;   // 1/sqrt(128)
    int base = head * 128 + lane * 4;

    float4 qv = *(const float4*)&g_q[node * DD + base];
    qv.x *= scale; qv.y *= scale; qv.z *= scale; qv.w *= scale;

    float mrun = -1e30f;
    float l = 0.f;
    float4 acc = make_float4(0.f, 0.f, 0.f, 0.f);

    const unsigned* bits = g_bits + node * WORDS;
#pragma unroll 4
    for (int wi = 0; wi < WORDS; ++wi) {
        unsigned word = bits[wi];   // uniform across warp -> broadcast
        while (word) {
            int b = __ffs(word) - 1;
            word &= word - 1;
            int m = (wi << 5) + b;

            const float4 kv = *(const float4*)&g_k[m * DD + base];
            float s = qv.x * kv.x + qv.y * kv.y + qv.z * kv.z + qv.w * kv.w;
            s += __shfl_xor_sync(0xffffffffu, s, 16);
            s += __shfl_xor_sync(0xffffffffu, s, 8);
            s += __shfl_xor_sync(0xffffffffu, s, 4);
            s += __shfl_xor_sync(0xffffffffu, s, 2);
            s += __shfl_xor_sync(0xffffffffu, s, 1);

            float nm    = fmaxf(mrun, s);
            float alpha = __expf(mrun - nm);
            float e     = __expf(s - nm);
            const float4 vv = *(const float4*)&g_v[m * DD + base];
            l = l * alpha + e;
            acc.x = acc.x * alpha + e * vv.x;
            acc.y = acc.y * alpha + e * vv.y;
            acc.z = acc.z * alpha + e * vv.z;
            acc.w = acc.w * alpha + e * vv.w;
            mrun = nm;
        }
    }
    float inv = 1.f / l;
    float4 o = make_float4(acc.x * inv, acc.y * inv, acc.z * inv, acc.w * inv);
    *(float4*)&g_vagg[node * DD + base] = o;
}

// ---------------- BatchNorm (training-mode, biased var), deterministic ------
__global__ void k_stats(int which) {   // which: 0 -> g_t1, 1 -> g_t0
    const float* X = which ? g_t0 : g_t1;
    int col = blockIdx.x;
    float s = 0.f, s2 = 0.f;
    for (int r = threadIdx.x; r < NN; r += 256) {
        float xv = X[r * DD + col];
        s += xv;
        s2 += xv * xv;
    }
    __shared__ float sh[256], sh2[256];
    sh[threadIdx.x] = s;
    sh2[threadIdx.x] = s2;
    __syncthreads();
    for (int off = 128; off > 0; off >>= 1) {
        if (threadIdx.x < off) {
            sh[threadIdx.x]  += sh[threadIdx.x + off];
            sh2[threadIdx.x] += sh2[threadIdx.x + off];
        }
        __syncthreads();
    }
    if (threadIdx.x == 0) {
        float m   = sh[0] * (1.f / NN);
        float var = sh2[0] * (1.f / NN) - m * m;
        g_mu[col]   = m;
        g_rstd[col] = rsqrtf(var + 1e-5f);
    }
}

__global__ void k_bnapply(const float* __restrict__ gam, const float* __restrict__ bet,
                          float* __restrict__ outp, int which) {
    int i = blockIdx.x * blockDim.x + threadIdx.x;
    if (i >= NN * DD) return;
    const float* X = which ? g_t0 : g_t1;
    float* Y = which ? outp : g_t1;
    int c = i & (DD - 1);
    float yv = (X[i] - g_mu[c]) * g_rstd[c] * gam[c] + bet[c];
    Y[i] = fmaxf(yv, 0.f);
}

// ---------------- launch -----------------------------------------------------
extern "C" void kernel_launch(void* const* d_in, const int* in_sizes, int n_in,
                              void* d_out, int out_size) {
    const float* x    = (const float*)d_in[0];
    const void*  ei   = d_in[1];
    const float* wq   = (const float*)d_in[2];
    const float* bq   = (const float*)d_in[3];
    const float* wk   = (const float*)d_in[4];
    const float* bk   = (const float*)d_in[5];
    const float* wv   = (const float*)d_in[6];
    const float* bv   = (const float*)d_in[7];
    const float* wo   = (const float*)d_in[8];
    const float* bo   = (const float*)d_in[9];
    const float* epsP = (const float*)d_in[10];
    const float* w1   = (const float*)d_in[11];
    const float* b1   = (const float*)d_in[12];
    const float* g1   = (const float*)d_in[13];
    const float* be1  = (const float*)d_in[14];
    const float* w2   = (const float*)d_in[15];
    const float* b2   = (const float*)d_in[16];
    const float* g2   = (const float*)d_in[17];
    const float* be2  = (const float*)d_in[18];
    float* out = (float*)d_out;

    int E = in_sizes[1] / 2;

    // 1. adjacency bitmask
    k_zero<<<(NN * WORDS + 255) / 256, 256>>>();
    k_detect<<<4, 256>>>((const int*)ei);
    k_build<<<(E + 255) / 256, 256>>>(ei, E);

    // 2. Q/K/V projections
    dim3 gq(DD / 64, NN / 64, 3);
    k_gemm_qkv<<<gq, 256>>>(x, wq, bq, wk, bk, wv, bv);

    // 3. sparse masked attention
    k_attn<<<(NN * 2 * 32) / 256, 256>>>();

    // 4. output projection + eps*x residual
    dim3 gg(DD / 64, NN / 64);
    k_gemm_wo<<<gg, 256>>>(wo, bo, x, epsP);

    // 5. FFN layer 1 + BN + ReLU
    k_gemm_w1<<<gg, 256>>>(w1, b1);
    k_stats<<<DD, 256>>>(0);
    k_bnapply<<<(NN * DD + 255) / 256, 256>>>(g1, be1, nullptr, 0);

    // 6. FFN layer 2 + BN + ReLU -> output
    k_gemm_w2<<<gg, 256>>>(w2, b2);
    k_stats<<<DD, 256>>>(1);
    k_bnapply<<<(NN * DD + 255) / 256, 256>>>(g2, be2, out, 1);
}

// round 2
// speedup vs baseline: 1.0072x; 1.0072x over previous
#include <cuda_runtime.h>

#define NN 4096
#define DD 256
#define WORDS 128   // 4096 bits / 32

// ---------------- scratch (static device memory; no allocation) -------------
__device__ unsigned g_bits[NN * WORDS];   // 2 MB adjacency bitmask
__device__ int      g_is64;
__device__ float    g_q[NN * DD];
__device__ float    g_k[NN * DD];
__device__ float    g_v[NN * DD];
__device__ float    g_vagg[NN * DD];
__device__ float    g_t0[NN * DD];
__device__ float    g_t1[NN * DD];
__device__ float    g_mu[DD];
__device__ float    g_rstd[DD];

// ---------------- graph construction ----------------------------------------
__global__ void k_zero() {
    int i = blockIdx.x * blockDim.x + threadIdx.x;
    if (i < NN * WORDS) g_bits[i] = 0u;
    if (i == 0) g_is64 = 1;
}

// Decide whether edge_index is int64 or int32: if interpreted as int64 the
// first 1024 values must all be in [0, NN). With int32 data the hi halves are
// random node ids (nonzero w.p. 4095/4096 each) so the flag clears.
__global__ void k_detect(const int* __restrict__ e32) {
    int i = blockIdx.x * blockDim.x + threadIdx.x;   // 1024 threads
    int lo = e32[2 * i];
    int hi = e32[2 * i + 1];
    if (hi != 0 || lo < 0 || lo >= NN) atomicAnd(&g_is64, 0);
}

__global__ void k_build(const void* __restrict__ eptr, int E) {
    int i = blockIdx.x * blockDim.x + threadIdx.x;
    if (i >= E) return;
    int r, c;
    if (g_is64) {
        const long long* e = (const long long*)eptr;
        r = (int)e[i];
        c = (int)e[E + i];
    } else {
        const int* e = (const int*)eptr;
        r = e[i];
        c = e[E + i];
    }
    atomicOr(&g_bits[r * WORDS + (c >> 5)], 1u << (c & 31));
}

// ---------------- fp32 tiled GEMM: C[4096,256] = A[4096,256] @ B[256,256] ----
// BM=BN=64, BK=16, 256 threads, 4x4 per thread.
__device__ __forceinline__ void gemm_tile(const float* __restrict__ A,
                                          const float* __restrict__ B,
                                          const float* __restrict__ bias,
                                          float* __restrict__ C,
                                          const float* __restrict__ X,
                                          float eps) {
    __shared__ float As[16][64];
    __shared__ float Bs[16][64];

    int tid = threadIdx.x;
    int tx = tid & 15;        // 0..15 -> col quad
    int ty = tid >> 4;        // 0..15 -> row quad
    int rowBase = blockIdx.y * 64;
    int colBase = blockIdx.x * 64;

    int ar = tid >> 2;            // 0..63
    int ac = (tid & 3) * 4;       // 0,4,8,12
    int br = tid >> 4;            // 0..15
    int bc = (tid & 15) * 4;      // 0..60

    const float* Ag = A + (rowBase + ar) * DD + ac;
    const float* Bg = B + br * DD + colBase + bc;

    float acc[4][4];
#pragma unroll
    for (int i = 0; i < 4; i++)
#pragma unroll
        for (int j = 0; j < 4; j++) acc[i][j] = 0.f;

    for (int kk = 0; kk < DD; kk += 16) {
        float4 a = *(const float4*)(Ag + kk);
        float4 b = *(const float4*)(Bg + kk * DD);
        As[ac + 0][ar] = a.x;
        As[ac + 1][ar] = a.y;
        As[ac + 2][ar] = a.z;
        As[ac + 3][ar] = a.w;
        *(float4*)&Bs[br][bc] = b;
        __syncthreads();
#pragma unroll
        for (int kq = 0; kq < 16; ++kq) {
            float4 av = *(const float4*)&As[kq][ty * 4];
            float4 bv = *(const float4*)&Bs[kq][tx * 4];
            acc[0][0] += av.x * bv.x; acc[0][1] += av.x * bv.y;
            acc[0][2] += av.x * bv.z; acc[0][3] += av.x * bv.w;
            acc[1][0] += av.y * bv.x; acc[1][1] += av.y * bv.y;
            acc[1][2] += av.y * bv.z; acc[1][3] += av.y * bv.w;
            acc[2][0] += av.z * bv.x; acc[2][1] += av.z * bv.y;
            acc[2][2] += av.z * bv.z; acc[2][3] += av.z * bv.w;
            acc[3][0] += av.w * bv.x; acc[3][1] += av.w * bv.y;
            acc[3][2] += av.w * bv.z; acc[3][3] += av.w * bv.w;
        }
        __syncthreads();
    }

    int col0 = colBase + tx * 4;
    float4 bi = *(const float4*)&bias[col0];
#pragma unroll
    for (int i = 0; i < 4; i++) {
        int row = rowBase + ty * 4 + i;
        float4 o;
        o.x = acc[i][0] + bi.x;
        o.y = acc[i][1] + bi.y;
        o.z = acc[i][2] + bi.z;
        o.w = acc[i][3] + bi.w;
        if (X) {
            const float4 xv = *(const float4*)&X[row * DD + col0];
            o.x += eps * xv.x; o.y += eps * xv.y;
            o.z += eps * xv.z; o.w += eps * xv.w;
        }
        *(float4*)&C[row * DD + col0] = o;
    }
}

__global__ void k_gemm_qkv(const float* __restrict__ x,
                           const float* __restrict__ wq, const float* __restrict__ bq,
                           const float* __restrict__ wk, const float* __restrict__ bk,
                           const float* __restrict__ wv, const float* __restrict__ bv) {
    const float* B;
    const float* bi;
    float* C;
    if (blockIdx.z == 0)      { B = wq; bi = bq; C = g_q; }
    else if (blockIdx.z == 1) { B = wk; bi = bk; C = g_k; }
    else                      { B = wv; bi = bv; C = g_v; }
    gemm_tile(x, B, bi, C, nullptr, 0.f);
}

__global__ void k_gemm_wo(const float* __restrict__ wo, const float* __restrict__ bo,
                          const float* __restrict__ x, const float* __restrict__ epsP) {
    gemm_tile(g_vagg, wo, bo, g_t0, x, epsP[0]);
}

__global__ void k_gemm_w1(const float* __restrict__ w1, const float* __restrict__ b1) {
    gemm_tile(g_t0, w1, b1, g_t1, nullptr, 0.f);
}

__global__ void k_gemm_w2(const float* __restrict__ w2, const float* __restrict__ b2) {
    gemm_tile(g_t1, w2, b2, g_t0, nullptr, 0.f);
}

// ---------------- sparse masked attention (one warp per node,head) ----------
__global__ void k_attn() {
    int gw   = (blockIdx.x * blockDim.x + threadIdx.x) >> 5;
    int lane = threadIdx.x & 31;
    if (gw >= NN * 2) return;
    int node = gw >> 1;
    int head = gw & 1;

    const float scale = 0.08838834764831845f;   // 1/sqrt(128)
    int base = head * 128 + lane * 4;

    float4 qv = *(const float4*)&g_q[node * DD + base];
    qv.x *= scale; qv.y *= scale; qv.z *= scale; qv.w *= scale;

    float mrun = -1e30f;
    float l = 0.f;
    float4 acc = make_float4(0.f, 0.f, 0.f, 0.f);

    const unsigned* bits = g_bits + node * WORDS;
#pragma unroll 4
    for (int wi = 0; wi < WORDS; ++wi) {
        unsigned word = bits[wi];   // uniform across warp -> broadcast
        while (word) {
            int b = __ffs(word) - 1;
            word &= word - 1;
            int m = (wi << 5) + b;

            const float4 kv = *(const float4*)&g_k[m * DD + base];
            float s = qv.x * kv.x + qv.y * kv.y + qv.z * kv.z + qv.w * kv.w;
            s += __shfl_xor_sync(0xffffffffu, s, 16);
            s += __shfl_xor_sync(0xffffffffu, s, 8);
            s += __shfl_xor_sync(0xffffffffu, s, 4);
            s += __shfl_xor_sync(0xffffffffu, s, 2);
            s += __shfl_xor_sync(0xffffffffu, s, 1);

            float nm    = fmaxf(mrun, s);
            float alpha = __expf(mrun - nm);
            float e     = __expf(s - nm);
            const float4 vv = *(const float4*)&g_v[m * DD + base];
            l = l * alpha + e;
            acc.x = acc.x * alpha + e * vv.x;
            acc.y = acc.y * alpha + e * vv.y;
            acc.z = acc.z * alpha + e * vv.z;
            acc.w = acc.w * alpha + e * vv.w;
            mrun = nm;
        }
    }
    float inv = 1.f / l;
    float4 o = make_float4(acc.x * inv, acc.y * inv, acc.z * inv, acc.w * inv);
    *(float4*)&g_vagg[node * DD + base] = o;
}

// ---------------- BatchNorm (training-mode, biased var), deterministic ------
__global__ void k_stats(int which) {   // which: 0 -> g_t1, 1 -> g_t0
    const float* X = which ? g_t0 : g_t1;
    int col = blockIdx.x;
    float s = 0.f, s2 = 0.f;
    for (int r = threadIdx.x; r < NN; r += 256) {
        float xv = X[r * DD + col];
        s += xv;
        s2 += xv * xv;
    }
    __shared__ float sh[256], sh2[256];
    sh[threadIdx.x] = s;
    sh2[threadIdx.x] = s2;
    __syncthreads();
    for (int off = 128; off > 0; off >>= 1) {
        if (threadIdx.x < off) {
            sh[threadIdx.x]  += sh[threadIdx.x + off];
            sh2[threadIdx.x] += sh2[threadIdx.x + off];
        }
        __syncthreads();
    }
    if (threadIdx.x == 0) {
        float m   = sh[0] * (1.f / NN);
        float var = sh2[0] * (1.f / NN) - m * m;
        g_mu[col]   = m;
        g_rstd[col] = rsqrtf(var + 1e-5f);
    }
}

__global__ void k_bnapply(const float* __restrict__ gam, const float* __restrict__ bet,
                          float* __restrict__ outp, int which) {
    int i = blockIdx.x * blockDim.x + threadIdx.x;
    if (i >= NN * DD) return;
    const float* X = which ? g_t0 : g_t1;
    float* Y = which ? outp : g_t1;
    int c = i & (DD - 1);
    float yv = (X[i] - g_mu[c]) * g_rstd[c] * gam[c] + bet[c];
    Y[i] = fmaxf(yv, 0.f);
}

// ---------------- launch -----------------------------------------------------
extern "C" void kernel_launch(void* const* d_in, const int* in_sizes, int n_in,
                              void* d_out, int out_size) {
    const float* x    = (const float*)d_in[0];
    const void*  ei   = d_in[1];
    const float* wq   = (const float*)d_in[2];
    const float* bq   = (const float*)d_in[3];
    const float* wk   = (const float*)d_in[4];
    const float* bk   = (const float*)d_in[5];
    const float* wv   = (const float*)d_in[6];
    const float* bv   = (const float*)d_in[7];
    const float* wo   = (const float*)d_in[8];
    const float* bo   = (const float*)d_in[9];
    const float* epsP = (const float*)d_in[10];
    const float* w1   = (const float*)d_in[11];
    const float* b1   = (const float*)d_in[12];
    const float* g1   = (const float*)d_in[13];
    const float* be1  = (const float*)d_in[14];
    const float* w2   = (const float*)d_in[15];
    const float* b2   = (const float*)d_in[16];
    const float* g2   = (const float*)d_in[17];
    const float* be2  = (const float*)d_in[18];
    float* out = (float*)d_out;

    int E = in_sizes[1] / 2;

    // 1. adjacency bitmask
    k_zero<<<(NN * WORDS + 255) / 256, 256>>>();
    k_detect<<<4, 256>>>((const int*)ei);
    k_build<<<(E + 255) / 256, 256>>>(ei, E);

    // 2. Q/K/V projections
    dim3 gq(DD / 64, NN / 64, 3);
    k_gemm_qkv<<<gq, 256>>>(x, wq, bq, wk, bk, wv, bv);

    // 3. sparse masked attention
    k_attn<<<(NN * 2 * 32) / 256, 256>>>();

    // 4. output projection + eps*x residual
    dim3 gg(DD / 64, NN / 64);
    k_gemm_wo<<<gg, 256>>>(wo, bo, x, epsP);

    // 5. FFN layer 1 + BN + ReLU
    k_gemm_w1<<<gg, 256>>>(w1, b1);
    k_stats<<<DD, 256>>>(0);
    k_bnapply<<<(NN * DD + 255) / 256, 256>>>(g1, be1, nullptr, 0);

    // 6. FFN layer 2 + BN + ReLU -> output
    k_gemm_w2<<<gg, 256>>>(w2, b2);
    k_stats<<<DD, 256>>>(1);
    k_bnapply<<<(NN * DD + 255) / 256, 256>>>(g2, be2, out, 1);
}

// round 5
// speedup vs baseline: 1.3445x; 1.3349x over previous
#include <cuda_runtime.h>
#include <cuda_bf16.h>
#include <cstdint>

#define NN 4096
#define DD 256
#define WORDS 128
#define AST 72          // smem bf16 row stride (144B -> conflict-free frags)

// ---------------- scratch (static device memory) ----------------------------
__device__ unsigned g_bits[NN * WORDS];
__device__ int      g_is64;
__device__ float    g_q[NN * DD];
__device__ float    g_k[NN * DD];
__device__ float    g_v[NN * DD];
__device__ float    g_vagg[NN * DD];
__device__ float    g_t0[NN * DD];
__device__ float    g_t1[NN * DD];
__device__ float    g_mu[DD];
__device__ float    g_rstd[DD];
__device__ float    g_part[2 * 32 * DD];
__device__ __align__(16) __nv_bfloat16 g_wh[6 * DD * DD];  // [N][K] hi split
__device__ __align__(16) __nv_bfloat16 g_wl[6 * DD * DD];  // [N][K] lo split

#define SMEM_BYTES 55296   // (128+128+64+64) * 72 * 2

// ---------------- graph construction ----------------------------------------
__global__ void k_zero() {
    int i = blockIdx.x * blockDim.x + threadIdx.x;
    if (i < NN * WORDS) g_bits[i] = 0u;
    if (i == 0) g_is64 = 1;
}

__global__ void k_detect(const int* __restrict__ e32) {
    int i = blockIdx.x * blockDim.x + threadIdx.x;   // 1024 threads
    int lo = e32[2 * i];
    int hi = e32[2 * i + 1];
    if (hi != 0 || lo < 0 || lo >= NN) atomicAnd(&g_is64, 0);
}

__global__ void k_build(const void* __restrict__ eptr, int E) {
    int i = blockIdx.x * blockDim.x + threadIdx.x;
    if (i >= E) return;
    int r, c;
    if (g_is64) {
        const long long* e = (const long long*)eptr;
        r = (int)e[i];
        c = (int)e[E + i];
    } else {
        const int* e = (const int*)eptr;
        r = e[i];
        c = e[E + i];
    }
    atomicOr(&g_bits[r * WORDS + (c >> 5)], 1u << (c & 31));
}

// ---------------- weight prep: fp32 [K,N] -> bf16 hi/lo [N,K] ---------------
__global__ void k_prep(const float* __restrict__ wq, const float* __restrict__ wk,
                       const float* __restrict__ wv, const float* __restrict__ wo,
                       const float* __restrict__ w1, const float* __restrict__ w2) {
    int i = blockIdx.x * 256 + threadIdx.x;   // 6*65536 total
    int m = i >> 16;
    int e = i & 65535;
    const float* w = (m == 0) ? wq : (m == 1) ? wk : (m == 2) ? wv
                   : (m == 3) ? wo : (m == 4) ? w1 : w2;
    float f = w[e];                            // e = k*256 + n
    __nv_bfloat16 h = __float2bfloat16(f);
    __nv_bfloat16 l = __float2bfloat16(f - __bfloat162float(h));
    int k = e >> 8, n = e & 255;
    int o = (m << 16) + n * DD + k;
    g_wh[o] = h;
    g_wl[o] = l;
}

// ---------------- warp-MMA bf16 split GEMM -----------------------------------
__device__ __forceinline__ void hmma(float* d, const uint32_t* a, const uint32_t* b) {
    asm volatile(
        "mma.sync.aligned.m16n8k16.row.col.f32.bf16.bf16.f32 "
        "{%0,%1,%2,%3},{%4,%5,%6,%7},{%8,%9},{%0,%1,%2,%3};"
        : "+f"(d[0]), "+f"(d[1]), "+f"(d[2]), "+f"(d[3])
        : "r"(a[0]), "r"(a[1]), "r"(a[2]), "r"(a[3]), "r"(b[0]), "r"(b[1]));
}

__device__ __forceinline__ uint32_t pack2(float x, float y) {
    __nv_bfloat16 hx = __float2bfloat16(x);
    __nv_bfloat16 hy = __float2bfloat16(y);
    return (uint32_t)__bfloat16_as_ushort(hx) | ((uint32_t)__bfloat16_as_ushort(hy) << 16);
}

// C[tileRow:+128, nBase:+64] = A[:,0:256] @ W[:, nBase:+64] + bias (+ eps*X)
__device__ __forceinline__ void gemm_body(const float* __restrict__ A,
                                          const __nv_bfloat16* __restrict__ Wh,
                                          const __nv_bfloat16* __restrict__ Wl,
                                          const float* __restrict__ bias,
                                          float* __restrict__ C,
                                          const float* __restrict__ X,
                                          float epsv) {
    extern __shared__ __align__(16) char smem[];
    __nv_bfloat16* Ah = (__nv_bfloat16*)smem;      // [128][AST]
    __nv_bfloat16* Al = Ah + 128 * AST;            // [128][AST]
    __nv_bfloat16* Bh = Al + 128 * AST;            // [64][AST]
    __nv_bfloat16* Bl = Bh + 64 * AST;             // [64][AST]

    int tid = threadIdx.x;
    int w = tid >> 5, lane = tid & 31;
    int wm = w & 3, wn = w >> 2;       // warp grid 4(m) x 2(n)
    int g = lane >> 2, tg = lane & 3;
    int tileRow = blockIdx.y * 128;
    int nBase = blockIdx.x * 64;

    float acc[2][4][4];
#pragma unroll
    for (int mi = 0; mi < 2; ++mi)
#pragma unroll
        for (int ni = 0; ni < 4; ++ni)
#pragma unroll
            for (int r = 0; r < 4; ++r) acc[mi][ni][r] = 0.f;

    for (int c = 0; c < 4; ++c) {
        int k0 = c * 64;
        // ---- stage A chunk (fp32 -> hi/lo bf16) ----
#pragma unroll
        for (int i = 0; i < 8; ++i) {
            int idx = i * 256 + tid;
            int row = idx >> 4;
            int col = (idx & 15) << 2;
            float4 f = *(const float4*)(A + (size_t)(tileRow + row) * DD + k0 + col);
            float h0f = __bfloat162float(__float2bfloat16(f.x));
            float h1f = __bfloat162float(__float2bfloat16(f.y));
            float h2f = __bfloat162float(__float2bfloat16(f.z));
            float h3f = __bfloat162float(__float2bfloat16(f.w));
            uint2 hh = make_uint2(pack2(f.x, f.y), pack2(f.z, f.w));
            uint2 ll = make_uint2(pack2(f.x - h0f, f.y - h1f), pack2(f.z - h2f, f.w - h3f));
            *(uint2*)(Ah + row * AST + col) = hh;
            *(uint2*)(Al + row * AST + col) = ll;
        }
        // ---- stage B chunk (preconverted bf16 [N][K]) ----
#pragma unroll
        for (int i = 0; i < 2; ++i) {
            int idx = i * 256 + tid;
            int n = idx >> 3;
            int k = (idx & 7) << 3;
            uint4 vh = *(const uint4*)(Wh + (size_t)(nBase + n) * DD + k0 + k);
            uint4 vl = *(const uint4*)(Wl + (size_t)(nBase + n) * DD + k0 + k);
            *(uint2*)(Bh + n * AST + k)     = make_uint2(vh.x, vh.y);
            *(uint2*)(Bh + n * AST + k + 4) = make_uint2(vh.z, vh.w);
            *(uint2*)(Bl + n * AST + k)     = make_uint2(vl.x, vl.y);
            *(uint2*)(Bl + n * AST + k + 4) = make_uint2(vl.z, vl.w);
        }
        __syncthreads();

#pragma unroll
        for (int ks = 0; ks < 4; ++ks) {
            int kk = ks * 16 + 2 * tg;
            uint32_t ah[2][4], alr[2][4];
#pragma unroll
            for (int mi = 0; mi < 2; ++mi) {
                const __nv_bfloat16* p0 = Ah + (wm * 32 + mi * 16 + g) * AST + kk;
                const __nv_bfloat16* q0 = Al + (wm * 32 + mi * 16 + g) * AST + kk;
                ah[mi][0]  = *(const uint32_t*)p0;
                ah[mi][1]  = *(const uint32_t*)(p0 + 8 * AST);
                ah[mi][2]  = *(const uint32_t*)(p0 + 8);
                ah[mi][3]  = *(const uint32_t*)(p0 + 8 * AST + 8);
                alr[mi][0] = *(const uint32_t*)q0;
                alr[mi][1] = *(const uint32_t*)(q0 + 8 * AST);
                alr[mi][2] = *(const uint32_t*)(q0 + 8);
                alr[mi][3] = *(const uint32_t*)(q0 + 8 * AST + 8);
            }
            uint32_t bh[4][2], blr[4][2];
#pragma unroll
            for (int ni = 0; ni < 4; ++ni) {
                const __nv_bfloat16* p = Bh + (wn * 32 + ni * 8 + g) * AST + kk;
                const __nv_bfloat16* q = Bl + (wn * 32 + ni * 8 + g) * AST + kk;
                bh[ni][0]  = *(const uint32_t*)p;
                bh[ni][1]  = *(const uint32_t*)(p + 8);
                blr[ni][0] = *(const uint32_t*)q;
                blr[ni][1] = *(const uint32_t*)(q + 8);
            }
#pragma unroll
            for (int mi = 0; mi < 2; ++mi)
#pragma unroll
                for (int ni = 0; ni < 4; ++ni) {
                    hmma(acc[mi][ni], ah[mi], bh[ni]);
                    hmma(acc[mi][ni], ah[mi], blr[ni]);
                    hmma(acc[mi][ni], alr[mi], bh[ni]);
                }
        }
        __syncthreads();
    }

    // ---- epilogue ----
#pragma unroll
    for (int mi = 0; mi < 2; ++mi) {
        int r0 = tileRow + wm * 32 + mi * 16 + g;
#pragma unroll
        for (int ni = 0; ni < 4; ++ni) {
            int cg = nBase + wn * 32 + ni * 8 + 2 * tg;
            float2 b = *(const float2*)(bias + cg);
            float2 o0, o1;
            o0.x = acc[mi][ni][0] + b.x;
            o0.y = acc[mi][ni][1] + b.y;
            o1.x = acc[mi][ni][2] + b.x;
            o1.y = acc[mi][ni][3] + b.y;
            if (X) {
                float2 x0 = *(const float2*)(X + (size_t)r0 * DD + cg);
                float2 x1 = *(const float2*)(X + (size_t)(r0 + 8) * DD + cg);
                o0.x += epsv * x0.x; o0.y += epsv * x0.y;
                o1.x += epsv * x1.x; o1.y += epsv * x1.y;
            }
            *(float2*)(C + (size_t)r0 * DD + cg) = o0;
            *(float2*)(C + (size_t)(r0 + 8) * DD + cg) = o1;
        }
    }
}

__global__ void __launch_bounds__(256, 1)
k_hqkv(const float* __restrict__ x, const float* __restrict__ bq,
       const float* __restrict__ bk, const float* __restrict__ bv) {
    int z = blockIdx.z;
    const float* bias = (z == 0) ? bq : (z == 1) ? bk : bv;
    float* C = (z == 0) ? g_q : (z == 1) ? g_k : g_v;
    gemm_body(x, g_wh + z * 65536, g_wl + z * 65536, bias, C, nullptr, 0.f);
}

__global__ void __launch_bounds__(256, 1)
k_hgen(const float* __restrict__ xparam, int widx, const float* __restrict__ bias,
       int selA, int selC, int useres, const float* __restrict__ epsP) {
    const float* A = (selA == 1) ? g_vagg : (selA == 2) ? g_t0 : g_t1;
    float* C = (selC == 2) ? g_t0 : g_t1;
    const float* X = useres ? xparam : nullptr;
    float ev = useres ? epsP[0] : 0.f;
    gemm_body(A, g_wh + widx * 65536, g_wl + widx * 65536, bias, C, X, ev);
}

// ---------------- sparse masked attention (one warp per node,head) ----------
__global__ void k_attn() {
    int gw   = (blockIdx.x * blockDim.x + threadIdx.x) >> 5;
    int lane = threadIdx.x & 31;
    if (gw >= NN * 2) return;
    int node = gw >> 1;
    int head = gw & 1;

    const float scale = 0.08838834764831845f;   // 1/sqrt(128)
    int base = head * 128 + lane * 4;

    float4 qv = *(const float4*)&g_q[node * DD + base];
    qv.x *= scale; qv.y *= scale; qv.z *= scale; qv.w *= scale;

    float mrun = -1e30f;
    float l = 0.f;
    float4 acc = make_float4(0.f, 0.f, 0.f, 0.f);

    const unsigned* bits = g_bits + node * WORDS;
#pragma unroll 4
    for (int wi = 0; wi < WORDS; ++wi) {
        unsigned word = bits[wi];
        while (word) {
            int b = __ffs(word) - 1;
            word &= word - 1;
            int m = (wi << 5) + b;

            const float4 kv = *(const float4*)&g_k[m * DD + base];
            float s = qv.x * kv.x + qv.y * kv.y + qv.z * kv.z + qv.w * kv.w;
            s += __shfl_xor_sync(0xffffffffu, s, 16);
            s += __shfl_xor_sync(0xffffffffu, s, 8);
            s += __shfl_xor_sync(0xffffffffu, s, 4);
            s += __shfl_xor_sync(0xffffffffu, s, 2);
            s += __shfl_xor_sync(0xffffffffu, s, 1);

            float nm    = fmaxf(mrun, s);
            float alpha = __expf(mrun - nm);
            float e     = __expf(s - nm);
            const float4 vv = *(const float4*)&g_v[m * DD + base];
            l = l * alpha + e;
            acc.x = acc.x * alpha + e * vv.x;
            acc.y = acc.y * alpha + e * vv.y;
            acc.z = acc.z * alpha + e * vv.z;
            acc.w = acc.w * alpha + e * vv.w;
            mrun = nm;
        }
    }
    float inv = 1.f / l;
    float4 o = make_float4(acc.x * inv, acc.y * inv, acc.z * inv, acc.w * inv);
    *(float4*)&g_vagg[node * DD + base] = o;
}

// ---------------- BatchNorm stats: coalesced two-stage -----------------------
// which: 0 -> g_t1, 1 -> g_t0   (device-side selection; NO host symbol passing)
__global__ void k_statp(int which) {
    const float* X = which ? g_t0 : g_t1;
    int b = blockIdx.x;
    int c = threadIdx.x;
    float s = 0.f, s2 = 0.f;
    const float* p = X + (size_t)b * 128 * DD + c;
#pragma unroll 8
    for (int r = 0; r < 128; ++r) {
        float v = p[r * DD];
        s += v;
        s2 += v * v;
    }
    g_part[b * DD + c] = s;
    g_part[32 * DD + b * DD + c] = s2;
}

__global__ void k_statf() {
    int c = threadIdx.x;
    float s = 0.f, s2 = 0.f;
#pragma unroll
    for (int b = 0; b < 32; ++b) {
        s += g_part[b * DD + c];
        s2 += g_part[32 * DD + b * DD + c];
    }
    float m = s * (1.f / NN);
    float var = s2 * (1.f / NN) - m * m;
    g_mu[c] = m;
    g_rstd[c] = rsqrtf(var + 1e-5f);
}

// which: 0 -> X=g_t1, Y=g_t1 ; 1 -> X=g_t0, Y=outp
__global__ void k_bnapply(const float* __restrict__ gam, const float* __restrict__ bet,
                          float* __restrict__ outp, int which) {
    int i = blockIdx.x * blockDim.x + threadIdx.x;
    if (i >= NN * DD) return;
    const float* X = which ? g_t0 : g_t1;
    float* Y = which ? outp : g_t1;
    int c = i & (DD - 1);
    float yv = (X[i] - g_mu[c]) * g_rstd[c] * gam[c] + bet[c];
    Y[i] = fmaxf(yv, 0.f);
}

// ---------------- launch ------------------------------------------------------
extern "C" void kernel_launch(void* const* d_in, const int* in_sizes, int n_in,
                              void* d_out, int out_size) {
    const float* x    = (const float*)d_in[0];
    const void*  ei   = d_in[1];
    const float* wq   = (const float*)d_in[2];
    const float* bq   = (const float*)d_in[3];
    const float* wk   = (const float*)d_in[4];
    const float* bk   = (const float*)d_in[5];
    const float* wv   = (const float*)d_in[6];
    const float* bv   = (const float*)d_in[7];
    const float* wo   = (const float*)d_in[8];
    const float* bo   = (const float*)d_in[9];
    const float* epsP = (const float*)d_in[10];
    const float* w1   = (const float*)d_in[11];
    const float* b1   = (const float*)d_in[12];
    const float* g1   = (const float*)d_in[13];
    const float* be1  = (const float*)d_in[14];
    const float* w2   = (const float*)d_in[15];
    const float* b2   = (const float*)d_in[16];
    const float* g2   = (const float*)d_in[17];
    const float* be2  = (const float*)d_in[18];
    float* out = (float*)d_out;

    int E = in_sizes[1] / 2;

    cudaFuncSetAttribute(k_hqkv, cudaFuncAttributeMaxDynamicSharedMemorySize, SMEM_BYTES);
    cudaFuncSetAttribute(k_hgen, cudaFuncAttributeMaxDynamicSharedMemorySize, SMEM_BYTES);

    // 1. adjacency bitmask + weight prep
    k_zero<<<(NN * WORDS + 255) / 256, 256>>>();
    k_detect<<<4, 256>>>((const int*)ei);
    k_build<<<(E + 255) / 256, 256>>>(ei, E);
    k_prep<<<6 * 256, 256>>>(wq, wk, wv, wo, w1, w2);

    // 2. Q/K/V projections (tensor cores, split bf16)
    k_hqkv<<<dim3(4, 32, 3), 256, SMEM_BYTES>>>(x, bq, bk, bv);

    // 3. sparse masked attention
    k_attn<<<(NN * 2 * 32) / 256, 256>>>();

    // 4. output projection + eps*x residual
    k_hgen<<<dim3(4, 32), 256, SMEM_BYTES>>>(x, 3, bo, 1, 2, 1, epsP);

    // 5. FFN layer 1 + BN + ReLU
    k_hgen<<<dim3(4, 32), 256, SMEM_BYTES>>>(x, 4, b1, 2, 3, 0, epsP);
    k_statp<<<32, 256>>>(0);
    k_statf<<<1, 256>>>();
    k_bnapply<<<(NN * DD + 255) / 256, 256>>>(g1, be1, nullptr, 0);

    // 6. FFN layer 2 + BN + ReLU -> output
    k_hgen<<<dim3(4, 32), 256, SMEM_BYTES>>>(x, 5, b2, 3, 2, 0, epsP);
    k_statp<<<32, 256>>>(1);
    k_statf<<<1, 256>>>();
    k_bnapply<<<(NN * DD + 255) / 256, 256>>>(g2, be2, out, 1);
}

// round 6
// speedup vs baseline: 1.5889x; 1.1818x over previous
#include <cuda_runtime.h>
#include <cuda_bf16.h>
#include <cstdint>

#define NN 4096
#define DD 256
#define WORDS 128
#define AST 72          // smem bf16 row stride (144B -> conflict-free frags)

// ---------------- scratch (static device memory) ----------------------------
__device__ unsigned g_bits[NN * WORDS];
__device__ int      g_is64;
__device__ float    g_q[NN * DD];
__device__ float    g_k[NN * DD];
__device__ float    g_v[NN * DD];
__device__ float    g_vagg[NN * DD];
__device__ float    g_t0[NN * DD];
__device__ float    g_t1[NN * DD];
__device__ float    g_bnsc[DD];
__device__ float    g_bnsh[DD];
__device__ float    g_part[2 * 32 * DD];
__device__ __align__(16) __nv_bfloat16 g_wh[6 * DD * DD];  // [N][K] hi split
__device__ __align__(16) __nv_bfloat16 g_wl[6 * DD * DD];  // [N][K] lo split

#define SMEM_BYTES 55296   // (128+128+64+64) * 72 * 2

// ---------------- graph construction ----------------------------------------
__global__ void k_zero() {
    int i = blockIdx.x * blockDim.x + threadIdx.x;
    if (i < NN * WORDS) g_bits[i] = 0u;
    if (i == 0) g_is64 = 1;
}

__global__ void k_detect(const int* __restrict__ e32) {
    int i = blockIdx.x * blockDim.x + threadIdx.x;   // 1024 threads
    int lo = e32[2 * i];
    int hi = e32[2 * i + 1];
    if (hi != 0 || lo < 0 || lo >= NN) atomicAnd(&g_is64, 0);
}

__global__ void k_build(const void* __restrict__ eptr, int E) {
    int i = blockIdx.x * blockDim.x + threadIdx.x;
    if (i >= E) return;
    int r, c;
    if (g_is64) {
        const long long* e = (const long long*)eptr;
        r = (int)e[i];
        c = (int)e[E + i];
    } else {
        const int* e = (const int*)eptr;
        r = e[i];
        c = e[E + i];
    }
    atomicOr(&g_bits[r * WORDS + (c >> 5)], 1u << (c & 31));
}

__device__ __forceinline__ uint32_t pack2(float x, float y) {
    __nv_bfloat16 hx = __float2bfloat16(x);
    __nv_bfloat16 hy = __float2bfloat16(y);
    return (uint32_t)__bfloat16_as_ushort(hx) | ((uint32_t)__bfloat16_as_ushort(hy) << 16);
}

// ---------------- weight prep: fp32 [K,N] -> bf16 hi/lo [N,K], tiled ---------
// grid = 6 * 16 blocks (64x64 tiles), 256 threads
__global__ void k_prep(const float* __restrict__ wq, const float* __restrict__ wk,
                       const float* __restrict__ wv, const float* __restrict__ wo,
                       const float* __restrict__ w1, const float* __restrict__ w2) {
    __shared__ float t[64][65];
    int m = blockIdx.x >> 4;
    int tile = blockIdx.x & 15;
    int kBase = (tile >> 2) * 64;
    int nBase = (tile & 3) * 64;
    const float* w = (m == 0) ? wq : (m == 1) ? wk : (m == 2) ? wv
                   : (m == 3) ? wo : (m == 4) ? w1 : w2;
    int tid = threadIdx.x;
#pragma unroll
    for (int i = 0; i < 4; ++i) {
        int idx = i * 256 + tid;
        int r = idx >> 4;
        int c4 = (idx & 15) << 2;
        float4 f = *(const float4*)(w + (size_t)(kBase + r) * DD + nBase + c4);
        t[r][c4] = f.x; t[r][c4 + 1] = f.y; t[r][c4 + 2] = f.z; t[r][c4 + 3] = f.w;
    }
    __syncthreads();
#pragma unroll
    for (int i = 0; i < 4; ++i) {
        int idx = i * 256 + tid;
        int n = idx >> 4;
        int k4 = (idx & 15) << 2;
        float f0 = t[k4][n], f1 = t[k4 + 1][n], f2 = t[k4 + 2][n], f3 = t[k4 + 3][n];
        float h0 = __bfloat162float(__float2bfloat16(f0));
        float h1 = __bfloat162float(__float2bfloat16(f1));
        float h2 = __bfloat162float(__float2bfloat16(f2));
        float h3 = __bfloat162float(__float2bfloat16(f3));
        uint2 hh = make_uint2(pack2(f0, f1), pack2(f2, f3));
        uint2 ll = make_uint2(pack2(f0 - h0, f1 - h1), pack2(f2 - h2, f3 - h3));
        size_t o = ((size_t)m << 16) + (size_t)(nBase + n) * DD + kBase + k4;
        *(uint2*)(g_wh + o) = hh;
        *(uint2*)(g_wl + o) = ll;
    }
}

// ---------------- warp-MMA bf16 split GEMM -----------------------------------
__device__ __forceinline__ void hmma(float* d, const uint32_t* a, const uint32_t* b) {
    asm volatile(
        "mma.sync.aligned.m16n8k16.row.col.f32.bf16.bf16.f32 "
        "{%0,%1,%2,%3},{%4,%5,%6,%7},{%8,%9},{%0,%1,%2,%3};"
        : "+f"(d[0]), "+f"(d[1]), "+f"(d[2]), "+f"(d[3])
        : "r"(a[0]), "r"(a[1]), "r"(a[2]), "r"(a[3]), "r"(b[0]), "r"(b[1]));
}

// C[tileRow:+128, nBase:+64] = f(A)[:,0:256] @ W[:, nBase:+64] + bias (+ eps*X)
// bnA: apply y = relu(a*g_bnsc + g_bnsh) to A during load
// doStats: write per-CTA column sum/sumsq partials to g_part
__device__ __forceinline__ void gemm_body(const float* __restrict__ A,
                                          const __nv_bfloat16* __restrict__ Wh,
                                          const __nv_bfloat16* __restrict__ Wl,
                                          const float* __restrict__ bias,
                                          float* __restrict__ C,
                                          const float* __restrict__ X,
                                          float epsv, int bnA, int doStats) {
    extern __shared__ __align__(16) char smem[];
    __nv_bfloat16* Ah = (__nv_bfloat16*)smem;      // [128][AST]
    __nv_bfloat16* Al = Ah + 128 * AST;            // [128][AST]
    __nv_bfloat16* Bh = Al + 128 * AST;            // [64][AST]
    __nv_bfloat16* Bl = Bh + 64 * AST;             // [64][AST]

    int tid = threadIdx.x;
    int w = tid >> 5, lane = tid & 31;
    int wm = w & 3, wn = w >> 2;       // warp grid 4(m) x 2(n)
    int g = lane >> 2, tg = lane & 3;
    int tileRow = blockIdx.y * 128;
    int nBase = blockIdx.x * 64;

    float acc[2][4][4];
#pragma unroll
    for (int mi = 0; mi < 2; ++mi)
#pragma unroll
        for (int ni = 0; ni < 4; ++ni)
#pragma unroll
            for (int r = 0; r < 4; ++r) acc[mi][ni][r] = 0.f;

    for (int c = 0; c < 4; ++c) {
        int k0 = c * 64;
        // ---- stage A chunk (fp32 -> hi/lo bf16, optional fused BN+ReLU) ----
#pragma unroll
        for (int i = 0; i < 8; ++i) {
            int idx = i * 256 + tid;
            int row = idx >> 4;
            int col = (idx & 15) << 2;
            float4 f = *(const float4*)(A + (size_t)(tileRow + row) * DD + k0 + col);
            if (bnA) {
                float4 sc = *(const float4*)(g_bnsc + k0 + col);
                float4 sh = *(const float4*)(g_bnsh + k0 + col);
                f.x = fmaxf(f.x * sc.x + sh.x, 0.f);
                f.y = fmaxf(f.y * sc.y + sh.y, 0.f);
                f.z = fmaxf(f.z * sc.z + sh.z, 0.f);
                f.w = fmaxf(f.w * sc.w + sh.w, 0.f);
            }
            float h0f = __bfloat162float(__float2bfloat16(f.x));
            float h1f = __bfloat162float(__float2bfloat16(f.y));
            float h2f = __bfloat162float(__float2bfloat16(f.z));
            float h3f = __bfloat162float(__float2bfloat16(f.w));
            uint2 hh = make_uint2(pack2(f.x, f.y), pack2(f.z, f.w));
            uint2 ll = make_uint2(pack2(f.x - h0f, f.y - h1f), pack2(f.z - h2f, f.w - h3f));
            *(uint2*)(Ah + row * AST + col) = hh;
            *(uint2*)(Al + row * AST + col) = ll;
        }
        // ---- stage B chunk (preconverted bf16 [N][K]) ----
#pragma unroll
        for (int i = 0; i < 2; ++i) {
            int idx = i * 256 + tid;
            int n = idx >> 3;
            int k = (idx & 7) << 3;
            uint4 vh = *(const uint4*)(Wh + (size_t)(nBase + n) * DD + k0 + k);
            uint4 vl = *(const uint4*)(Wl + (size_t)(nBase + n) * DD + k0 + k);
            *(uint2*)(Bh + n * AST + k)     = make_uint2(vh.x, vh.y);
            *(uint2*)(Bh + n * AST + k + 4) = make_uint2(vh.z, vh.w);
            *(uint2*)(Bl + n * AST + k)     = make_uint2(vl.x, vl.y);
            *(uint2*)(Bl + n * AST + k + 4) = make_uint2(vl.z, vl.w);
        }
        __syncthreads();

#pragma unroll
        for (int ks = 0; ks < 4; ++ks) {
            int kk = ks * 16 + 2 * tg;
            uint32_t ah[2][4], alr[2][4];
#pragma unroll
            for (int mi = 0; mi < 2; ++mi) {
                const __nv_bfloat16* p0 = Ah + (wm * 32 + mi * 16 + g) * AST + kk;
                const __nv_bfloat16* q0 = Al + (wm * 32 + mi * 16 + g) * AST + kk;
                ah[mi][0]  = *(const uint32_t*)p0;
                ah[mi][1]  = *(const uint32_t*)(p0 + 8 * AST);
                ah[mi][2]  = *(const uint32_t*)(p0 + 8);
                ah[mi][3]  = *(const uint32_t*)(p0 + 8 * AST + 8);
                alr[mi][0] = *(const uint32_t*)q0;
                alr[mi][1] = *(const uint32_t*)(q0 + 8 * AST);
                alr[mi][2] = *(const uint32_t*)(q0 + 8);
                alr[mi][3] = *(const uint32_t*)(q0 + 8 * AST + 8);
            }
            uint32_t bh[4][2], blr[4][2];
#pragma unroll
            for (int ni = 0; ni < 4; ++ni) {
                const __nv_bfloat16* p = Bh + (wn * 32 + ni * 8 + g) * AST + kk;
                const __nv_bfloat16* q = Bl + (wn * 32 + ni * 8 + g) * AST + kk;
                bh[ni][0]  = *(const uint32_t*)p;
                bh[ni][1]  = *(const uint32_t*)(p + 8);
                blr[ni][0] = *(const uint32_t*)q;
                blr[ni][1] = *(const uint32_t*)(q + 8);
            }
#pragma unroll
            for (int mi = 0; mi < 2; ++mi)
#pragma unroll
                for (int ni = 0; ni < 4; ++ni) {
                    hmma(acc[mi][ni], ah[mi], bh[ni]);
                    hmma(acc[mi][ni], ah[mi], blr[ni]);
                    hmma(acc[mi][ni], alr[mi], bh[ni]);
                }
        }
        __syncthreads();
    }

    // ---- epilogue (+ optional fused per-CTA column stats) ----
    float ssum[4][2], ssq[4][2];
#pragma unroll
    for (int ni = 0; ni < 4; ++ni) { ssum[ni][0] = ssum[ni][1] = 0.f; ssq[ni][0] = ssq[ni][1] = 0.f; }

#pragma unroll
    for (int mi = 0; mi < 2; ++mi) {
        int r0 = tileRow + wm * 32 + mi * 16 + g;
#pragma unroll
        for (int ni = 0; ni < 4; ++ni) {
            int cg = nBase + wn * 32 + ni * 8 + 2 * tg;
            float2 b = *(const float2*)(bias + cg);
            float2 o0, o1;
            o0.x = acc[mi][ni][0] + b.x;
            o0.y = acc[mi][ni][1] + b.y;
            o1.x = acc[mi][ni][2] + b.x;
            o1.y = acc[mi][ni][3] + b.y;
            if (X) {
                float2 x0 = *(const float2*)(X + (size_t)r0 * DD + cg);
                float2 x1 = *(const float2*)(X + (size_t)(r0 + 8) * DD + cg);
                o0.x += epsv * x0.x; o0.y += epsv * x0.y;
                o1.x += epsv * x1.x; o1.y += epsv * x1.y;
            }
            *(float2*)(C + (size_t)r0 * DD + cg) = o0;
            *(float2*)(C + (size_t)(r0 + 8) * DD + cg) = o1;
            if (doStats) {
                ssum[ni][0] += o0.x + o1.x;
                ssum[ni][1] += o0.y + o1.y;
                ssq[ni][0]  += o0.x * o0.x + o1.x * o1.x;
                ssq[ni][1]  += o0.y * o0.y + o1.y * o1.y;
            }
        }
    }

    if (doStats) {
        // reduce over g lanes (offsets 4, 8, 16 toggle the g bits)
#pragma unroll
        for (int ni = 0; ni < 4; ++ni)
#pragma unroll
            for (int cc = 0; cc < 2; ++cc) {
                float s = ssum[ni][cc], q2 = ssq[ni][cc];
#pragma unroll
                for (int off = 16; off >= 4; off >>= 1) {
                    s  += __shfl_xor_sync(0xffffffffu, s, off);
                    q2 += __shfl_xor_sync(0xffffffffu, q2, off);
                }
                ssum[ni][cc] = s; ssq[ni][cc] = q2;
            }
        float* sred = (float*)smem;          // [4 wm][64] sum, +256: sq
        __syncthreads();
        if (g == 0) {
#pragma unroll
            for (int ni = 0; ni < 4; ++ni) {
                int col = wn * 32 + ni * 8 + 2 * tg;
                sred[wm * 64 + col]           = ssum[ni][0];
                sred[wm * 64 + col + 1]       = ssum[ni][1];
                sred[256 + wm * 64 + col]     = ssq[ni][0];
                sred[256 + wm * 64 + col + 1] = ssq[ni][1];
            }
        }
        __syncthreads();
        if (tid < 64) {
            float s = sred[tid] + sred[64 + tid] + sred[128 + tid] + sred[192 + tid];
            float q2 = sred[256 + tid] + sred[320 + tid] + sred[384 + tid] + sred[448 + tid];
            g_part[blockIdx.y * DD + nBase + tid] = s;
            g_part[32 * DD + blockIdx.y * DD + nBase + tid] = q2;
        }
    }
}

__global__ void __launch_bounds__(256, 1)
k_hqkv(const float* __restrict__ x, const float* __restrict__ bq,
       const float* __restrict__ bk, const float* __restrict__ bv) {
    int z = blockIdx.z;
    const float* bias = (z == 0) ? bq : (z == 1) ? bk : bv;
    float* C = (z == 0) ? g_q : (z == 1) ? g_k : g_v;
    gemm_body(x, g_wh + z * 65536, g_wl + z * 65536, bias, C, nullptr, 0.f, 0, 0);
}

__global__ void __launch_bounds__(256, 1)
k_hgen(const float* __restrict__ xparam, int widx, const float* __restrict__ bias,
       int selA, int selC, int useres, const float* __restrict__ epsP,
       int bnA, int doStats) {
    const float* A = (selA == 1) ? g_vagg : (selA == 2) ? g_t0 : g_t1;
    float* C = (selC == 2) ? g_t0 : g_t1;
    const float* X = useres ? xparam : nullptr;
    float ev = useres ? epsP[0] : 0.f;
    gemm_body(A, g_wh + widx * 65536, g_wl + widx * 65536, bias, C, X, ev, bnA, doStats);
}

// ---------------- sparse masked attention (one warp per node,head) ----------
__global__ void k_attn() {
    int gw   = (blockIdx.x * blockDim.x + threadIdx.x) >> 5;
    int lane = threadIdx.x & 31;
    if (gw >= NN * 2) return;
    int node = gw >> 1;
    int head = gw & 1;

    const float scale = 0.08838834764831845f;   // 1/sqrt(128)
    int base = head * 128 + lane * 4;

    float4 qv = *(const float4*)&g_q[node * DD + base];
    qv.x *= scale; qv.y *= scale; qv.z *= scale; qv.w *= scale;

    float mrun = -1e30f;
    float l = 0.f;
    float4 acc = make_float4(0.f, 0.f, 0.f, 0.f);

    const unsigned* bits = g_bits + node * WORDS;
#pragma unroll 4
    for (int wi = 0; wi < WORDS; ++wi) {
        unsigned word = bits[wi];
        while (word) {
            int b = __ffs(word) - 1;
            word &= word - 1;
            int m = (wi << 5) + b;

            const float4 kv = *(const float4*)&g_k[m * DD + base];
            float s = qv.x * kv.x + qv.y * kv.y + qv.z * kv.z + qv.w * kv.w;
            s += __shfl_xor_sync(0xffffffffu, s, 16);
            s += __shfl_xor_sync(0xffffffffu, s, 8);
            s += __shfl_xor_sync(0xffffffffu, s, 4);
            s += __shfl_xor_sync(0xffffffffu, s, 2);
            s += __shfl_xor_sync(0xffffffffu, s, 1);

            float nm    = fmaxf(mrun, s);
            float alpha = __expf(mrun - nm);
            float e     = __expf(s - nm);
            const float4 vv = *(const float4*)&g_v[m * DD + base];
            l = l * alpha + e;
            acc.x = acc.x * alpha + e * vv.x;
            acc.y = acc.y * alpha + e * vv.y;
            acc.z = acc.z * alpha + e * vv.z;
            acc.w = acc.w * alpha + e * vv.w;
            mrun = nm;
        }
    }
    float inv = 1.f / l;
    float4 o = make_float4(acc.x * inv, acc.y * inv, acc.z * inv, acc.w * inv);
    *(float4*)&g_vagg[node * DD + base] = o;
}

// ---------------- BN finalize: mu/rstd -> per-channel scale/shift ------------
__global__ void k_statf(const float* __restrict__ gam, const float* __restrict__ bet) {
    int c = threadIdx.x;
    float s = 0.f, s2 = 0.f;
#pragma unroll
    for (int b = 0; b < 32; ++b) {
        s += g_part[b * DD + c];
        s2 += g_part[32 * DD + b * DD + c];
    }
    float m = s * (1.f / NN);
    float var = s2 * (1.f / NN) - m * m;
    float rstd = rsqrtf(var + 1e-5f);
    float sc = rstd * gam[c];
    g_bnsc[c] = sc;
    g_bnsh[c] = bet[c] - m * sc;
}

// final BN apply + ReLU: out = relu(t0 * sc + sh)
__global__ void k_bnout(float* __restrict__ outp) {
    int i = blockIdx.x * blockDim.x + threadIdx.x;
    if (i >= NN * DD) return;
    int c = i & (DD - 1);
    outp[i] = fmaxf(g_t0[i] * g_bnsc[c] + g_bnsh[c], 0.f);
}

// ---------------- launch ------------------------------------------------------
extern "C" void kernel_launch(void* const* d_in, const int* in_sizes, int n_in,
                              void* d_out, int out_size) {
    const float* x    = (const float*)d_in[0];
    const void*  ei   = d_in[1];
    const float* wq   = (const float*)d_in[2];
    const float* bq   = (const float*)d_in[3];
    const float* wk   = (const float*)d_in[4];
    const float* bk   = (const float*)d_in[5];
    const float* wv   = (const float*)d_in[6];
    const float* bv   = (const float*)d_in[7];
    const float* wo   = (const float*)d_in[8];
    const float* bo   = (const float*)d_in[9];
    const float* epsP = (const float*)d_in[10];
    const float* w1   = (const float*)d_in[11];
    const float* b1   = (const float*)d_in[12];
    const float* g1   = (const float*)d_in[13];
    const float* be1  = (const float*)d_in[14];
    const float* w2   = (const float*)d_in[15];
    const float* b2   = (const float*)d_in[16];
    const float* g2   = (const float*)d_in[17];
    const float* be2  = (const float*)d_in[18];
    float* out = (float*)d_out;

    int E = in_sizes[1] / 2;

    cudaFuncSetAttribute(k_hqkv, cudaFuncAttributeMaxDynamicSharedMemorySize, SMEM_BYTES);
    cudaFuncSetAttribute(k_hgen, cudaFuncAttributeMaxDynamicSharedMemorySize, SMEM_BYTES);

    // 1. adjacency bitmask + weight prep
    k_zero<<<(NN * WORDS + 255) / 256, 256>>>();
    k_detect<<<4, 256>>>((const int*)ei);
    k_build<<<(E + 255) / 256, 256>>>(ei, E);
    k_prep<<<96, 256>>>(wq, wk, wv, wo, w1, w2);

    // 2. Q/K/V projections (tensor cores, split bf16)
    k_hqkv<<<dim3(4, 32, 3), 256, SMEM_BYTES>>>(x, bq, bk, bv);

    // 3. sparse masked attention
    k_attn<<<(NN * 2 * 32) / 256, 256>>>();

    // 4. output projection + eps*x residual  (vagg @ wo -> t0)
    k_hgen<<<dim3(4, 32), 256, SMEM_BYTES>>>(x, 3, bo, 1, 2, 1, epsP, 0, 0);

    // 5. FFN layer 1 (t0 @ w1 -> t1) + fused column stats
    k_hgen<<<dim3(4, 32), 256, SMEM_BYTES>>>(x, 4, b1, 2, 3, 0, epsP, 0, 1);
    k_statf<<<1, 256>>>(g1, be1);

    // 6. FFN layer 2 with fused BN1+ReLU on A (t1 -> t0) + fused column stats
    k_hgen<<<dim3(4, 32), 256, SMEM_BYTES>>>(x, 5, b2, 3, 2, 0, epsP, 1, 1);
    k_statf<<<1, 256>>>(g2, be2);

    // 7. final BN apply + ReLU -> out
    k_bnout<<<(NN * DD + 255) / 256, 256>>>(out);
}